// round 13
// baseline (speedup 1.0000x reference)
#include <cuda_runtime.h>
#include <math.h>

#define NN   302
#define TT   2048
#define TT4  512
#define KK   33
#define TEX  2080
#define NOD  16
#define DTs  0.2f
#define CROP 16
#define NTs  ((size_t)NN * TT)
#define NNP  312            // global list capacity

#define CONV_BLOCKS (NN * 4)   // 1208
#define SPAR_BLOCKS 76

#define RSTRIDE 36             // padded smem row stride (floats), float4-aligned
#define NSPLIT  4
#define NCHUNK  64             // 2048 / 32
#define REC_BLOCKS (NCHUNK * NSPLIT)        // 256
#define EPI_BLOCKS (REC_BLOCKS + NN)        // 558

// ---------------- scratch (static device globals; no allocs) ----------------
__device__ int   g_cnt[2 * NN];          // padded to multiple of 8
__device__ int   g_col[2][NN][NNP];      // raw column indices
__device__ float g_valw[2][NN][NNP];

#define SEL(c, nx, j) ((j)==0?(c).x:(j)==1?(c).y:(j)==2?(c).z:(j)==3?(c).w: \
                       (j)==4?(nx).x:(j)==5?(nx).y:(j)==6?(nx).z:(nx).w)

// ============================================================================
// K_A: conv blocks [0, CONV_BLOCKS): inline sensory + depthwise convs +
//      VAE sample + softplus (sections 2,3,4,5,8), R=4 outputs/thread.
//      spar blocks [CONV_BLOCKS, +SPAR_BLOCKS): sparsify W_chem/W_elec.
// ============================================================================
__global__ void __launch_bounds__(128)
k_main(const float* __restrict__ fr,
       const float* __restrict__ odor,
       const float* __restrict__ Wenc,
       const float* __restrict__ benc,
       const float* __restrict__ mask,
       const float* __restrict__ eps,
       const float* __restrict__ Wmf, const float* __restrict__ Wms,
       const float* __restrict__ bmu,
       const float* __restrict__ Wlf, const float* __restrict__ Wls,
       const float* __restrict__ blv,
       const float* __restrict__ waff, const float* __restrict__ baff,
       const float* __restrict__ Wc, const float* __restrict__ We,
       float* __restrict__ out)
{
    const int tx = threadIdx.x;

    if (blockIdx.x >= CONV_BLOCKS) {
        // ---- sparsify: warp per matrix row, ballot compaction, pad to 8 ----
        const int lane = tx & 31;
        const int m = (blockIdx.x - CONV_BLOCKS) * 4 + (tx >> 5);
        if (m >= NN) return;
        int c0 = 0, c1 = 0;
        for (int jb = 0; jb < NN; jb += 32) {
            const int j = jb + lane;
            float v = (j < NN) ? Wc[m * NN + j] : 0.0f;
            unsigned mk = __ballot_sync(0xffffffffu, v != 0.0f);
            if (v != 0.0f) {
                int p = c0 + __popc(mk & ((1u << lane) - 1u));
                g_col[0][m][p] = j; g_valw[0][m][p] = v;
            }
            c0 += __popc(mk);
            float w = (j < NN) ? We[m * NN + j] : 0.0f;
            mk = __ballot_sync(0xffffffffu, w != 0.0f);
            if (w != 0.0f) {
                int p = c1 + __popc(mk & ((1u << lane) - 1u));
                g_col[1][m][p] = j; g_valw[1][m][p] = w;
            }
            c1 += __popc(mk);
        }
        int c0p = (c0 + 7) & ~7;
        int c1p = (c1 + 7) & ~7;
        if (lane < c0p - c0) { g_col[0][m][c0 + lane] = 0; g_valw[0][m][c0 + lane] = 0.f; }
        if (lane < c1p - c1) { g_col[1][m][c1 + lane] = 0; g_valw[1][m][c1 + lane] = 0.f; }
        if (lane == 0) { g_cnt[m] = c0p; g_cnt[NN + m] = c1p; }
        return;
    }

    // ---------------- conv branch ----------------
    __shared__ float s_fr[560];
    __shared__ float s_se[560];
    __shared__ float4 s_w4[KK];
    const int n  = blockIdx.x >> 2;
    const int t0 = (blockIdx.x & 3) * 512;

    const float4* wep = (const float4*)(Wenc + n * NOD);
    const float4 w0 = __ldg(&wep[0]), w1 = __ldg(&wep[1]);
    const float4 w2 = __ldg(&wep[2]), w3 = __ldg(&wep[3]);
    const float msk = mask[n];
    const float be  = benc[n];

    {
        float4* sfr4 = (float4*)s_fr;
        float4* sse4 = (float4*)s_se;
        const float4* fr4 = (const float4*)(fr + n * TEX + t0);
        for (int v = tx; v < 136; v += 128) {
            sfr4[v] = fr4[v];
            float4 acc = make_float4(0.f, 0.f, 0.f, 0.f);
#pragma unroll
            for (int o = 0; o < NOD; ++o) {
                float we;
                if (o < 8)  we = SEL(w0, w1, o);
                else        we = SEL(w2, w3, o - 8);
                const float4 ov = ((const float4*)(odor + o * TEX + t0))[v];
                acc.x = fmaf(ov.x, we, acc.x);
                acc.y = fmaf(ov.y, we, acc.y);
                acc.z = fmaf(ov.z, we, acc.z);
                acc.w = fmaf(ov.w, we, acc.w);
            }
            sse4[v] = make_float4(msk * (acc.x + be), msk * (acc.y + be),
                                  msk * (acc.z + be), msk * (acc.w + be));
        }
    }
    if (tx < KK)
        s_w4[tx] = make_float4(Wmf[n * KK + tx], Wms[n * KK + tx],
                               Wlf[n * KK + tx], Wls[n * KK + tx]);
    __syncthreads();

    const float4* f4 = (const float4*)s_fr;
    const float4* e4 = (const float4*)s_se;
    const int q = tx;
    float4 fc = f4[q], fn = f4[q + 1];
    float4 ec = e4[q], en = e4[q + 1];

    float am[4] = {0,0,0,0}, bm[4] = {0,0,0,0};
    float cl[4] = {0,0,0,0}, dl[4] = {0,0,0,0};

#pragma unroll 33
    for (int k = 0; k < KK; ++k) {
        const float4 w = s_w4[k];
        const int sub = k & 3;
#pragma unroll
        for (int r = 0; r < 4; ++r) {
            const float xf = SEL(fc, fn, sub + r);
            const float xe = SEL(ec, en, sub + r);
            am[r] = fmaf(xf, w.x, am[r]);
            bm[r] = fmaf(xe, w.y, bm[r]);
            cl[r] = fmaf(xf, w.z, cl[r]);
            dl[r] = fmaf(xe, w.w, dl[r]);
        }
        if (sub == 3) {
            fc = fn; fn = f4[q + (k >> 2) + 2];
            ec = en; en = e4[q + (k >> 2) + 2];
        }
    }

    const float bmu_n = bmu[n], blv_n = blv[n];
    const float wa = waff[n], ba = baff[n];
    const size_t idx4 = (size_t)n * TT4 + (t0 >> 2) + tx;
    const float4 ep = ((const float4*)eps)[idx4];

    float4 mu, lv, sv, ca;
    mu.x = am[0] + bm[0] + bmu_n;  mu.y = am[1] + bm[1] + bmu_n;
    mu.z = am[2] + bm[2] + bmu_n;  mu.w = am[3] + bm[3] + bmu_n;
    lv.x = cl[0] + dl[0] + blv_n;  lv.y = cl[1] + dl[1] + blv_n;
    lv.z = cl[2] + dl[2] + blv_n;  lv.w = cl[3] + dl[3] + blv_n;
    sv.x = fmaf(expf(0.5f * lv.x), ep.x, mu.x);
    sv.y = fmaf(expf(0.5f * lv.y), ep.y, mu.y);
    sv.z = fmaf(expf(0.5f * lv.z), ep.z, mu.z);
    sv.w = fmaf(expf(0.5f * lv.w), ep.w, mu.w);
    {
        float z;
        z = fmaf(wa, sv.x, ba); ca.x = fmaxf(z, 0.f) + log1pf(expf(-fabsf(z)));
        z = fmaf(wa, sv.y, ba); ca.y = fmaxf(z, 0.f) + log1pf(expf(-fabsf(z)));
        z = fmaf(wa, sv.z, ba); ca.z = fmaxf(z, 0.f) + log1pf(expf(-fabsf(z)));
        z = fmaf(wa, sv.w, ba); ca.w = fmaxf(z, 0.f) + log1pf(expf(-fabsf(z)));
    }
    ((float4*)(out + 2 * NTs))[idx4] = mu;
    ((float4*)(out + 3 * NTs))[idx4] = lv;
    ((float4*)(out + 4 * NTs))[idx4] = sv;
    ((float4*)(out + 5 * NTs))[idx4] = ca;
    ((float4*)(out + 8 * NTs))[idx4] = e4[q + (CROP >> 2)];
}

// ============================================================================
// K_B: blocks [0,256): dense-smem-tile recurrent — block stages ALL 302 sv
//      rows for a 32-t chunk into smem; warps compute output neurons of one
//      of 4 neuron-splits reading sources from smem (conflict-free).
//      blocks [256,558): exponential IIR scan (256 thr, seg=8).
// ============================================================================
__global__ void __launch_bounds__(256)
k_epi(const float* __restrict__ bias,
      const float* __restrict__ tau,
      const float* __restrict__ ffull,
      const float* __restrict__ ctau,
      const float* __restrict__ scale,
      const float* __restrict__ shift,
      float* __restrict__ out)
{
    __shared__ float pool[NN * RSTRIDE];     // 10872 floats = 43.5 KB
    __shared__ float sF[8], sE[8];
    const int tx = threadIdx.x;

    if (blockIdx.x >= REC_BLOCKS) {
        // ---------------- scan branch: seg=8, P(i)=i+(i>>3) ----------------
        const int n    = blockIdx.x - REC_BLOCKS;
        const int w    = tx >> 5;
        const int lane = tx & 31;
        float* sbuf = pool;                  // needs 2304 floats

        const float* ca = out + 5 * NTs + (size_t)n * TT;
        for (int i = tx; i < TT; i += 256)
            sbuf[i + (i >> 3)] = ca[i];
        __syncthreads();

        const float r = expf(-DTs / ctau[n]);
        float f = r; f *= f; f *= f; f *= f;      // r^8

        const int base = tx * 9;
        float e = 0.f;
#pragma unroll
        for (int j = 0; j < 8; ++j)
            e = fmaf(r, e, sbuf[base + j]);

        float F = f, E = e;
#pragma unroll
        for (int dd = 1; dd < 32; dd <<= 1) {
            float Fp = __shfl_up_sync(0xffffffffu, F, dd);
            float Ep = __shfl_up_sync(0xffffffffu, E, dd);
            if (lane >= dd) { E = fmaf(F, Ep, E); F = F * Fp; }
        }
        if (lane == 31) { sF[w] = F; sE[w] = E; }
        __syncthreads();

        float Fp = 1.f, Ep = 0.f;
        for (int qq = 0; qq < w; ++qq) {
            Ep = fmaf(sF[qq], Ep, sE[qq]);
            Fp = Fp * sF[qq];
        }

        const float init = (ffull[(size_t)n * TT] - shift[n]) / scale[n];
        const float x0   = init / r;              // m[-1] seed: m[0] = init + ca[0]
        const float pv   = fmaf(Fp, x0, Ep);

        float Fe = __shfl_up_sync(0xffffffffu, F, 1);
        float Ee = __shfl_up_sync(0xffffffffu, E, 1);
        float carry = (lane == 0) ? pv : fmaf(Fe, pv, Ee);

        float cacc = carry;
#pragma unroll
        for (int j = 0; j < 8; ++j) {
            cacc = fmaf(r, cacc, sbuf[base + j]);
            sbuf[base + j] = cacc;
        }
        __syncthreads();

        const float sc = scale[n], sh = shift[n];
        float* o6 = out + 6 * NTs + (size_t)n * TT;
        float* o1 = out + 1 * NTs + (size_t)n * TT;
        for (int i = tx; i < TT; i += 256) {
            float m = sbuf[i + (i >> 3)];
            o6[i] = m;
            o1[i] = fmaf(sc, m, sh);
        }
        return;
    }

    // ---------------- recurrent branch ----------------
    const int chunk = blockIdx.x >> 2;          // 0..63, 32-t chunk
    const int split = blockIdx.x & 3;           // 0..3 neuron split
    const int v0    = chunk * 8;                // float4 offset within row

    // stage all 302 rows' 32-float chunk (2416 float4 loads, coalesced)
    {
        float4* sm4 = (float4*)pool;
        const float4* svg = (const float4*)(out + 4 * NTs);
        for (int v = tx; v < NN * 8; v += 256) {
            const int rrow = v >> 3, c = v & 7;
            sm4[rrow * (RSTRIDE / 4) + c] = svg[(size_t)rrow * TT4 + v0 + c];
        }
    }
    __syncthreads();

    const int lane = tx & 31;
    const int w    = tx >> 5;
    const int nbase = split * 76;
    const int ncount = (NN - nbase < 76) ? (NN - nbase) : 76;
    const int t = chunk * 32 + lane;

    for (int k = w; k < ncount; k += 8) {
        const int n = nbase + k;
        const int nc = __ldg(&g_cnt[n]);
        const int ne = __ldg(&g_cnt[NN + n]);

        float A = 0.f;
        for (int i = 0; i < nc; i += 8) {
            float x[8], vv[8];
#pragma unroll
            for (int u = 0; u < 8; ++u) {
                const int c = __ldg(&g_col[0][n][i + u]);
                vv[u] = __ldg(&g_valw[0][n][i + u]);
                x[u] = pool[c * RSTRIDE + lane];
            }
#pragma unroll
            for (int u = 0; u < 8; ++u)
                A = fmaf(vv[u], fmaxf(x[u], 0.f), A);
        }
        for (int i = 0; i < ne; i += 8) {
            float x[8], vv[8];
#pragma unroll
            for (int u = 0; u < 8; ++u) {
                const int c = __ldg(&g_col[1][n][i + u]);
                vv[u] = __ldg(&g_valw[1][n][i + u]);
                x[u] = pool[c * RSTRIDE + lane];
            }
#pragma unroll
            for (int u = 0; u < 8; ++u)
                A = fmaf(vv[u], x[u], A);
        }

        const float sen = out[8 * NTs + (size_t)n * TT + t];
        const float sv  = pool[n * RSTRIDE + lane];
        const float rec = A + sen;
        const float g   = DTs / __ldg(&tau[n]);
        const float bi  = __ldg(&bias[n]);
        out[7 * NTs + (size_t)n * TT + t] = rec;
        out[0 * NTs + (size_t)n * TT + t] = sv + g * (-sv + rec + bi);
    }
}

// ---------------- launch ----------------------------------------------------
extern "C" void kernel_launch(void* const* d_in, const int* in_sizes, int n_in,
                              void* d_out, int out_size)
{
    const float* fr    = (const float*)d_in[0];
    const float* ffull = (const float*)d_in[1];
    const float* odor  = (const float*)d_in[2];
    const float* eps   = (const float*)d_in[3];
    const float* Wenc  = (const float*)d_in[4];
    const float* benc  = (const float*)d_in[5];
    const float* mask  = (const float*)d_in[6];
    const float* Wmf   = (const float*)d_in[7];
    const float* Wms   = (const float*)d_in[8];
    const float* bmu   = (const float*)d_in[9];
    const float* Wlf   = (const float*)d_in[10];
    const float* Wls   = (const float*)d_in[11];
    const float* blv   = (const float*)d_in[12];
    const float* Wc    = (const float*)d_in[13];
    const float* We    = (const float*)d_in[14];
    const float* bias  = (const float*)d_in[15];
    const float* tau   = (const float*)d_in[16];
    const float* waff  = (const float*)d_in[17];
    const float* baff  = (const float*)d_in[18];
    const float* scale = (const float*)d_in[19];
    const float* shift = (const float*)d_in[20];
    const float* ctau  = (const float*)d_in[21];
    float* out = (float*)d_out;

    k_main<<<CONV_BLOCKS + SPAR_BLOCKS, 128>>>(fr, odor, Wenc, benc, mask, eps,
                                               Wmf, Wms, bmu, Wlf, Wls, blv,
                                               waff, baff, Wc, We, out);
    k_epi<<<EPI_BLOCKS, 256>>>(bias, tau, ffull, ctau, scale, shift, out);
}

// round 14
// speedup vs baseline: 1.6977x; 1.6977x over previous
#include <cuda_runtime.h>
#include <math.h>

#define NN   302
#define TT   2048
#define TT4  512
#define KK   33
#define TEX  2080
#define NOD  16
#define DTs  0.2f
#define CROP 16
#define NTs  ((size_t)NN * TT)
#define NNP  312            // global list capacity
#define LCAP 128            // smem list capacity

#define CONV_BLOCKS (NN * 4)   // 1208: 128 thr x 4 outputs = 512 t per block
#define SPAR_BLOCKS 76         // 4 warps per 128-thr block, warp per row

#define SCAN_BLOCKS NN                      // 302, first in grid
#define REC_BLOCKS  (NN * 2)                // 604 half-row blocks
#define EPI_BLOCKS  (SCAN_BLOCKS + REC_BLOCKS)   // 906

// ---------------- scratch (static device globals; no allocs) ----------------
__device__ int   g_cnt[2 * NN];          // padded to multiple of 8
__device__ int   g_col[2][NN][NNP];      // PRE-SCALED offsets col*TT4
__device__ float g_valw[2][NN][NNP];

// select element j (0..7) from pair of float4s (compile-time j after unroll)
#define SEL(c, nx, j) ((j)==0?(c).x:(j)==1?(c).y:(j)==2?(c).z:(j)==3?(c).w: \
                       (j)==4?(nx).x:(j)==5?(nx).y:(j)==6?(nx).z:(nx).w)

// ============================================================================
// K_A: conv blocks [0, CONV_BLOCKS): inline sensory + depthwise convs +
//      VAE sample + softplus (sections 2,3,4,5,8), R=4 outputs/thread.
//      spar blocks [CONV_BLOCKS, +SPAR_BLOCKS): sparsify W_chem/W_elec.
// ============================================================================
__global__ void __launch_bounds__(128)
k_main(const float* __restrict__ fr,
       const float* __restrict__ odor,
       const float* __restrict__ Wenc,
       const float* __restrict__ benc,
       const float* __restrict__ mask,
       const float* __restrict__ eps,
       const float* __restrict__ Wmf, const float* __restrict__ Wms,
       const float* __restrict__ bmu,
       const float* __restrict__ Wlf, const float* __restrict__ Wls,
       const float* __restrict__ blv,
       const float* __restrict__ waff, const float* __restrict__ baff,
       const float* __restrict__ Wc, const float* __restrict__ We,
       float* __restrict__ out)
{
    const int tx = threadIdx.x;

    if (blockIdx.x >= CONV_BLOCKS) {
        // ---- sparsify: warp per matrix row, ballot compaction, pad to 8 ----
        // stores offsets col*TT4 (pre-scaled for the rec kernel)
        const int lane = tx & 31;
        const int m = (blockIdx.x - CONV_BLOCKS) * 4 + (tx >> 5);
        if (m >= NN) return;
        int c0 = 0, c1 = 0;
        for (int jb = 0; jb < NN; jb += 32) {
            const int j = jb + lane;
            float v = (j < NN) ? Wc[m * NN + j] : 0.0f;
            unsigned mk = __ballot_sync(0xffffffffu, v != 0.0f);
            if (v != 0.0f) {
                int p = c0 + __popc(mk & ((1u << lane) - 1u));
                g_col[0][m][p] = j * TT4; g_valw[0][m][p] = v;
            }
            c0 += __popc(mk);
            float w = (j < NN) ? We[m * NN + j] : 0.0f;
            mk = __ballot_sync(0xffffffffu, w != 0.0f);
            if (w != 0.0f) {
                int p = c1 + __popc(mk & ((1u << lane) - 1u));
                g_col[1][m][p] = j * TT4; g_valw[1][m][p] = w;
            }
            c1 += __popc(mk);
        }
        int c0p = (c0 + 7) & ~7;
        int c1p = (c1 + 7) & ~7;
        if (lane < c0p - c0) { g_col[0][m][c0 + lane] = 0; g_valw[0][m][c0 + lane] = 0.f; }
        if (lane < c1p - c1) { g_col[1][m][c1 + lane] = 0; g_valw[1][m][c1 + lane] = 0.f; }
        if (lane == 0) { g_cnt[m] = c0p; g_cnt[NN + m] = c1p; }
        return;
    }

    // ---------------- conv branch ----------------
    __shared__ float s_fr[560];          // 544 used (512 + 32 halo)
    __shared__ float s_se[560];
    __shared__ float4 s_w4[KK];
    const int n  = blockIdx.x >> 2;
    const int t0 = (blockIdx.x & 3) * 512;

    const float4* wep = (const float4*)(Wenc + n * NOD);
    const float4 w0 = __ldg(&wep[0]), w1 = __ldg(&wep[1]);
    const float4 w2 = __ldg(&wep[2]), w3 = __ldg(&wep[3]);
    const float msk = mask[n];
    const float be  = benc[n];

    {
        float4* sfr4 = (float4*)s_fr;
        float4* sse4 = (float4*)s_se;
        const float4* fr4 = (const float4*)(fr + n * TEX + t0);
        for (int v = tx; v < 136; v += 128) {
            sfr4[v] = fr4[v];
            float4 acc = make_float4(0.f, 0.f, 0.f, 0.f);
#pragma unroll
            for (int o = 0; o < NOD; ++o) {
                float we;
                if (o < 8)  we = SEL(w0, w1, o);
                else        we = SEL(w2, w3, o - 8);
                const float4 ov = ((const float4*)(odor + o * TEX + t0))[v];
                acc.x = fmaf(ov.x, we, acc.x);
                acc.y = fmaf(ov.y, we, acc.y);
                acc.z = fmaf(ov.z, we, acc.z);
                acc.w = fmaf(ov.w, we, acc.w);
            }
            sse4[v] = make_float4(msk * (acc.x + be), msk * (acc.y + be),
                                  msk * (acc.z + be), msk * (acc.w + be));
        }
    }
    if (tx < KK)
        s_w4[tx] = make_float4(Wmf[n * KK + tx], Wms[n * KK + tx],
                               Wlf[n * KK + tx], Wls[n * KK + tx]);
    __syncthreads();

    const float4* f4 = (const float4*)s_fr;
    const float4* e4 = (const float4*)s_se;
    const int q = tx;
    float4 fc = f4[q], fn = f4[q + 1];
    float4 ec = e4[q], en = e4[q + 1];

    float am[4] = {0,0,0,0}, bm[4] = {0,0,0,0};
    float cl[4] = {0,0,0,0}, dl[4] = {0,0,0,0};

#pragma unroll 33
    for (int k = 0; k < KK; ++k) {
        const float4 w = s_w4[k];
        const int sub = k & 3;
#pragma unroll
        for (int r = 0; r < 4; ++r) {
            const float xf = SEL(fc, fn, sub + r);
            const float xe = SEL(ec, en, sub + r);
            am[r] = fmaf(xf, w.x, am[r]);
            bm[r] = fmaf(xe, w.y, bm[r]);
            cl[r] = fmaf(xf, w.z, cl[r]);
            dl[r] = fmaf(xe, w.w, dl[r]);
        }
        if (sub == 3) {
            fc = fn; fn = f4[q + (k >> 2) + 2];
            ec = en; en = e4[q + (k >> 2) + 2];
        }
    }

    const float bmu_n = bmu[n], blv_n = blv[n];
    const float wa = waff[n], ba = baff[n];
    const size_t idx4 = (size_t)n * TT4 + (t0 >> 2) + tx;
    const float4 ep = ((const float4*)eps)[idx4];

    float4 mu, lv, sv, ca;
    mu.x = am[0] + bm[0] + bmu_n;  mu.y = am[1] + bm[1] + bmu_n;
    mu.z = am[2] + bm[2] + bmu_n;  mu.w = am[3] + bm[3] + bmu_n;
    lv.x = cl[0] + dl[0] + blv_n;  lv.y = cl[1] + dl[1] + blv_n;
    lv.z = cl[2] + dl[2] + blv_n;  lv.w = cl[3] + dl[3] + blv_n;
    sv.x = fmaf(expf(0.5f * lv.x), ep.x, mu.x);
    sv.y = fmaf(expf(0.5f * lv.y), ep.y, mu.y);
    sv.z = fmaf(expf(0.5f * lv.z), ep.z, mu.z);
    sv.w = fmaf(expf(0.5f * lv.w), ep.w, mu.w);
    {
        float z;
        z = fmaf(wa, sv.x, ba); ca.x = fmaxf(z, 0.f) + log1pf(expf(-fabsf(z)));
        z = fmaf(wa, sv.y, ba); ca.y = fmaxf(z, 0.f) + log1pf(expf(-fabsf(z)));
        z = fmaf(wa, sv.z, ba); ca.z = fmaxf(z, 0.f) + log1pf(expf(-fabsf(z)));
        z = fmaf(wa, sv.w, ba); ca.w = fmaxf(z, 0.f) + log1pf(expf(-fabsf(z)));
    }
    ((float4*)(out + 2 * NTs))[idx4] = mu;
    ((float4*)(out + 3 * NTs))[idx4] = lv;
    ((float4*)(out + 4 * NTs))[idx4] = sv;
    ((float4*)(out + 5 * NTs))[idx4] = ca;
    ((float4*)(out + 8 * NTs))[idx4] = e4[q + (CROP >> 2)];
}

// ============================================================================
// K_B: blocks [0,302):   exponential IIR scan (256 thr, seg=8) — FIRST so the
//                        two populations interleave from wave 0;
//      blocks [302,906): sparse recurrent, half-row per block (256 thr,
//                        1 float4/thread, MLP-8, pre-scaled offsets).
// ============================================================================
__global__ void __launch_bounds__(256)
k_epi(const float* __restrict__ bias,
      const float* __restrict__ tau,
      const float* __restrict__ ffull,
      const float* __restrict__ ctau,
      const float* __restrict__ scale,
      const float* __restrict__ shift,
      float* __restrict__ out)
{
    const int tx = threadIdx.x;

    if (blockIdx.x < SCAN_BLOCKS) {
        // ---------------- scan branch: seg=8, P(i)=i+(i>>3) ----------------
        __shared__ float sbuf[TT + TT / 8];
        __shared__ float sF[8], sE[8];
        const int n    = blockIdx.x;
        const int w    = tx >> 5;
        const int lane = tx & 31;

        const float* ca = out + 5 * NTs + (size_t)n * TT;
        for (int i = tx; i < TT; i += 256)
            sbuf[i + (i >> 3)] = ca[i];
        __syncthreads();

        const float r = expf(-DTs / ctau[n]);
        float f = r; f *= f; f *= f; f *= f;      // r^8

        const int base = tx * 9;
        float e = 0.f;
#pragma unroll
        for (int j = 0; j < 8; ++j)
            e = fmaf(r, e, sbuf[base + j]);

        float F = f, E = e;
#pragma unroll
        for (int dd = 1; dd < 32; dd <<= 1) {
            float Fp = __shfl_up_sync(0xffffffffu, F, dd);
            float Ep = __shfl_up_sync(0xffffffffu, E, dd);
            if (lane >= dd) { E = fmaf(F, Ep, E); F = F * Fp; }
        }
        if (lane == 31) { sF[w] = F; sE[w] = E; }
        __syncthreads();

        float Fp = 1.f, Ep = 0.f;
        for (int qq = 0; qq < w; ++qq) {
            Ep = fmaf(sF[qq], Ep, sE[qq]);
            Fp = Fp * sF[qq];
        }

        const float init = (ffull[(size_t)n * TT] - shift[n]) / scale[n];
        const float x0   = init / r;              // m[-1] seed: m[0] = init + ca[0]
        const float pv   = fmaf(Fp, x0, Ep);

        float Fe = __shfl_up_sync(0xffffffffu, F, 1);
        float Ee = __shfl_up_sync(0xffffffffu, E, 1);
        float carry = (lane == 0) ? pv : fmaf(Fe, pv, Ee);

        float cacc = carry;
#pragma unroll
        for (int j = 0; j < 8; ++j) {
            cacc = fmaf(r, cacc, sbuf[base + j]);
            sbuf[base + j] = cacc;
        }
        __syncthreads();

        const float sc = scale[n], sh = shift[n];
        float* o6 = out + 6 * NTs + (size_t)n * TT;
        float* o1 = out + 1 * NTs + (size_t)n * TT;
        for (int i = tx; i < TT; i += 256) {
            float m = sbuf[i + (i >> 3)];
            o6[i] = m;
            o1[i] = fmaf(sc, m, sh);
        }
        return;
    }

    // ---------------- recurrent branch: half-row, 1 float4/thread ----------
    __shared__ int   sc_off[LCAP], se_off[LCAP];
    __shared__ float sc_val[LCAP], se_val[LCAP];
    const int b  = blockIdx.x - SCAN_BLOCKS;
    const int n  = b >> 1;
    const int t4 = (b & 1) * 256 + tx;

    const int nc = g_cnt[n];
    const int ne = g_cnt[NN + n];
    if (tx < nc) { sc_off[tx] = g_col[0][n][tx]; sc_val[tx] = g_valw[0][n][tx]; }
    if (tx < ne) { se_off[tx] = g_col[1][n][tx]; se_val[tx] = g_valw[1][n][tx]; }
    __syncthreads();

    const float4* sv4 = (const float4*)(out + 4 * NTs) + t4;

    float4 A = make_float4(0.f, 0.f, 0.f, 0.f);
    for (int i = 0; i < nc; i += 8) {
        float4 x[8];
#pragma unroll
        for (int u = 0; u < 8; ++u)
            x[u] = sv4[sc_off[i + u]];
#pragma unroll
        for (int u = 0; u < 8; ++u) {
            const float v = sc_val[i + u];
            A.x = fmaf(v, fmaxf(x[u].x, 0.f), A.x);
            A.y = fmaf(v, fmaxf(x[u].y, 0.f), A.y);
            A.z = fmaf(v, fmaxf(x[u].z, 0.f), A.z);
            A.w = fmaf(v, fmaxf(x[u].w, 0.f), A.w);
        }
    }
    for (int i = 0; i < ne; i += 8) {
        float4 x[8];
#pragma unroll
        for (int u = 0; u < 8; ++u)
            x[u] = sv4[se_off[i + u]];
#pragma unroll
        for (int u = 0; u < 8; ++u) {
            const float v = se_val[i + u];
            A.x = fmaf(v, x[u].x, A.x);  A.y = fmaf(v, x[u].y, A.y);
            A.z = fmaf(v, x[u].z, A.z);  A.w = fmaf(v, x[u].w, A.w);
        }
    }

    const float g  = DTs / tau[n];
    const float bi = bias[n];
    const size_t ridx = (size_t)n * TT4 + t4;
    float4 sen = ((const float4*)(out + 8 * NTs))[ridx];
    float4 sv  = ((const float4*)(out + 4 * NTs))[ridx];
    float4 rec, mun;
    rec.x = A.x + sen.x;  rec.y = A.y + sen.y;
    rec.z = A.z + sen.z;  rec.w = A.w + sen.w;
    mun.x = sv.x + g * (-sv.x + rec.x + bi);
    mun.y = sv.y + g * (-sv.y + rec.y + bi);
    mun.z = sv.z + g * (-sv.z + rec.z + bi);
    mun.w = sv.w + g * (-sv.w + rec.w + bi);
    ((float4*)(out + 7 * NTs))[ridx] = rec;
    ((float4*)(out + 0 * NTs))[ridx] = mun;
}

// ---------------- launch ----------------------------------------------------
extern "C" void kernel_launch(void* const* d_in, const int* in_sizes, int n_in,
                              void* d_out, int out_size)
{
    const float* fr    = (const float*)d_in[0];
    const float* ffull = (const float*)d_in[1];
    const float* odor  = (const float*)d_in[2];
    const float* eps   = (const float*)d_in[3];
    const float* Wenc  = (const float*)d_in[4];
    const float* benc  = (const float*)d_in[5];
    const float* mask  = (const float*)d_in[6];
    const float* Wmf   = (const float*)d_in[7];
    const float* Wms   = (const float*)d_in[8];
    const float* bmu   = (const float*)d_in[9];
    const float* Wlf   = (const float*)d_in[10];
    const float* Wls   = (const float*)d_in[11];
    const float* blv   = (const float*)d_in[12];
    const float* Wc    = (const float*)d_in[13];
    const float* We    = (const float*)d_in[14];
    const float* bias  = (const float*)d_in[15];
    const float* tau   = (const float*)d_in[16];
    const float* waff  = (const float*)d_in[17];
    const float* baff  = (const float*)d_in[18];
    const float* scale = (const float*)d_in[19];
    const float* shift = (const float*)d_in[20];
    const float* ctau  = (const float*)d_in[21];
    float* out = (float*)d_out;

    k_main<<<CONV_BLOCKS + SPAR_BLOCKS, 128>>>(fr, odor, Wenc, benc, mask, eps,
                                               Wmf, Wms, bmu, Wlf, Wls, blv,
                                               waff, baff, Wc, We, out);
    k_epi<<<EPI_BLOCKS, 256>>>(bias, tau, ffull, ctau, scale, shift, out);
}